// round 8
// baseline (speedup 1.0000x reference)
#include <cuda_runtime.h>
#include <cstdint>

// RayTransform: local_pos = (pos - trans) @ R, local_dir = dir @ R
// R = exp(skew(rot_vec)). N = 16777216 rays, ~805 MB HBM traffic.
// Persistent double-buffered pipeline: 912 blocks, each streams ~36 tiles.
// cp.async.cg (gmem->smem, L1-bypass) keeps loads for tile i+1 in flight
// while tile i is computed and stored -> no per-tile DRAM cold-start bubble.

#define THREADS 256
#define F4_PER_TILE (THREADS * 3)  // 768 float4 per tile (1024 rays)
#define GRID 912                   // 152 SMs * 6 resident blocks

__device__ __forceinline__ void cp_async16(uint32_t smem_addr, const void* gptr) {
    asm volatile("cp.async.cg.shared.global [%0], [%1], 16;\n"
                 :: "r"(smem_addr), "l"(gptr) : "memory");
}
__device__ __forceinline__ void cp_commit() {
    asm volatile("cp.async.commit_group;\n" ::: "memory");
}
template <int N>
__device__ __forceinline__ void cp_wait() {
    asm volatile("cp.async.wait_group %0;\n" :: "n"(N) : "memory");
}

__global__ void __launch_bounds__(THREADS, 6)
ray_transform_kernel(const float4* __restrict__ pos,
                     const float4* __restrict__ dir,
                     float4* __restrict__ out_pos,
                     float4* __restrict__ out_dir,
                     const float* __restrict__ rot_vec,
                     const float* __restrict__ trans,
                     int tiles_per_stream) {
    __shared__ float4 buf[2][F4_PER_TILE];
    __shared__ float sR[12];

    const int t = threadIdx.x;
    const int total_tiles = tiles_per_stream * 2;

    if (t == 0) {
        float x = rot_vec[0], y = rot_vec[1], z = rot_vec[2];
        float theta2 = x * x + y * y + z * z;
        float theta = sqrtf(theta2);
        float a, b;
        if (theta < 1e-8f) {
            a = 1.0f - theta2 / 6.0f;
            b = 0.5f - theta2 / 24.0f;
        } else {
            a = sinf(theta) / theta;
            b = (1.0f - cosf(theta)) / theta2;
        }
        sR[0] = 1.0f - b * (y * y + z * z);
        sR[1] = -a * z + b * x * y;
        sR[2] =  a * y + b * x * z;
        sR[3] =  a * z + b * x * y;
        sR[4] = 1.0f - b * (x * x + z * z);
        sR[5] = -a * x + b * y * z;
        sR[6] = -a * y + b * x * z;
        sR[7] =  a * x + b * y * z;
        sR[8] = 1.0f - b * (x * x + y * y);
        sR[9]  = trans[0];
        sR[10] = trans[1];
        sR[11] = trans[2];
    }

    // Issue async loads for one tile into buffer `bi` (one commit group).
    auto issue_tile = [&](int tile, int bi) {
        const bool is_pos = tile < tiles_per_stream;
        const float4* __restrict__ in = is_pos ? pos : dir;
        const size_t g =
            (size_t)(is_pos ? tile : tile - tiles_per_stream) * F4_PER_TILE;
        uint32_t s = (uint32_t)__cvta_generic_to_shared(&buf[bi][t]);
        cp_async16(s,                    in + g + t);
        cp_async16(s + THREADS * 16,     in + g + t + THREADS);
        cp_async16(s + 2 * THREADS * 16, in + g + t + 2 * THREADS);
        cp_commit();
    };

    const int tile0 = blockIdx.x;
    if (tile0 >= total_tiles) return;
    issue_tile(tile0, 0);

    int cur = 0;
    for (int tile = tile0; tile < total_tiles; tile += GRID) {
        const int next = tile + GRID;
        if (next < total_tiles) {
            issue_tile(next, cur ^ 1);  // buf[cur^1] safe: prev-iter tail sync
            cp_wait<1>();               // drain buf[cur]'s group, keep next's
        } else {
            cp_wait<0>();
        }
        __syncthreads();  // buf[cur] visible to all warps (and sR, iter 0)

        const bool is_pos = tile < tiles_per_stream;
        const float R0 = sR[0], R1 = sR[1], R2 = sR[2];
        const float R3 = sR[3], R4 = sR[4], R5 = sR[5];
        const float R6 = sR[6], R7 = sR[7], R8 = sR[8];
        const float t0 = is_pos ? sR[9]  : 0.0f;
        const float t1 = is_pos ? sR[10] : 0.0f;
        const float t2 = is_pos ? sR[11] : 0.0f;

        // Thread t owns float4s 3t..3t+2 (4 rays); word stride 12 is
        // conflict-free for LDS/STS.128. In-place same-thread RMW: no
        // barrier needed between the read and write-back.
        {
            float4 a = buf[cur][t * 3];
            float4 b = buf[cur][t * 3 + 1];
            float4 c = buf[cur][t * 3 + 2];
            float px[4] = {a.x, a.w, b.z, c.y};
            float py[4] = {a.y, b.x, b.w, c.z};
            float pz[4] = {a.z, b.y, c.x, c.w};
            float ox[4], oy[4], oz[4];
#pragma unroll
            for (int k = 0; k < 4; k++) {
                float x = px[k] - t0;
                float y = py[k] - t1;
                float z = pz[k] - t2;
                ox[k] = fmaf(x, R0, fmaf(y, R3, z * R6));
                oy[k] = fmaf(x, R1, fmaf(y, R4, z * R7));
                oz[k] = fmaf(x, R2, fmaf(y, R5, z * R8));
            }
            buf[cur][t * 3]     = make_float4(ox[0], oy[0], oz[0], ox[1]);
            buf[cur][t * 3 + 1] = make_float4(oy[1], oz[1], ox[2], oy[2]);
            buf[cur][t * 3 + 2] = make_float4(oz[2], ox[3], oy[3], oz[3]);
        }
        __syncthreads();  // per-thread writes -> cross-thread coalesced reads

        float4* __restrict__ outp = is_pos ? out_pos : out_dir;
        const size_t g =
            (size_t)(is_pos ? tile : tile - tiles_per_stream) * F4_PER_TILE;
        outp[g + t]               = buf[cur][t];
        outp[g + t + THREADS]     = buf[cur][t + THREADS];
        outp[g + t + 2 * THREADS] = buf[cur][t + 2 * THREADS];

        cur ^= 1;
        __syncthreads();  // all reads of old buf done before cp.async refills it
    }
}

extern "C" void kernel_launch(void* const* d_in, const int* in_sizes, int n_in,
                              void* d_out, int out_size) {
    const float* pos = (const float*)d_in[0];      // [N,3]
    const float* dir = (const float*)d_in[1];      // [N,3]
    const float* rot_vec = (const float*)d_in[2];  // [3]
    const float* trans = (const float*)d_in[3];    // [3]

    int n_f4 = in_sizes[0] / 4;  // N*3/4 float4 per stream
    float* out = (float*)d_out;
    float* out_pos = out;
    float* out_dir = out + (size_t)out_size / 2;

    int tiles_per_stream = n_f4 / F4_PER_TILE;  // 16384, exact
    ray_transform_kernel<<<GRID, THREADS>>>(
        (const float4*)pos, (const float4*)dir,
        (float4*)out_pos, (float4*)out_dir, rot_vec, trans,
        tiles_per_stream);
}

// round 9
// speedup vs baseline: 1.1642x; 1.1642x over previous
#include <cuda_runtime.h>

// RayTransform: local_pos = (pos - trans) @ R, local_dir = dir @ R
// R = exp(skew(rot_vec)). N = 16777216 rays, ~805 MB HBM traffic.
//
// Warp-autonomous version: each warp owns a contiguous 96-float4 chunk per
// stream (lane l <-> f4 chunk_base + l/+32/+64, perfectly coalesced), so the
// smem transpose never crosses warps. NO __syncthreads anywhere -> warps
// stream independently like a pure copy kernel. R computed per-thread
// (rot_vec is an L2-broadcast load; off the DRAM critical path).

#define THREADS 256
#define WARPS (THREADS / 32)
#define F4_PER_WARP 96                       // 128 rays per warp per stream
#define F4_PER_BLOCK (WARPS * F4_PER_WARP)   // 768

__global__ void __launch_bounds__(THREADS, 6)
ray_transform_kernel(const float4* __restrict__ pos,
                     const float4* __restrict__ dir,
                     float4* __restrict__ out_pos,
                     float4* __restrict__ out_dir,
                     const float* __restrict__ rot_vec,
                     const float* __restrict__ trans) {
    __shared__ float4 buf[WARPS][F4_PER_WARP];

    const int t = threadIdx.x;
    const int w = t >> 5;
    const int l = t & 31;

    // global chunk base for this warp (in float4 units, per stream)
    const size_t cbase = (size_t)blockIdx.x * F4_PER_BLOCK + w * F4_PER_WARP;

    // ---- all 6 coalesced LDG.128 in flight ----
    float4 p0 = pos[cbase + l];
    float4 p1 = pos[cbase + l + 32];
    float4 p2 = pos[cbase + l + 64];
    float4 d0 = dir[cbase + l];
    float4 d1 = dir[cbase + l + 32];
    float4 d2 = dir[cbase + l + 64];

    // ---- per-thread Rodrigues (uniform loads, broadcast) ----
    const float rx = rot_vec[0], ry = rot_vec[1], rz = rot_vec[2];
    const float theta2 = rx * rx + ry * ry + rz * rz;
    const float theta = sqrtf(theta2);
    float a, b;
    if (theta < 1e-8f) {
        a = 1.0f - theta2 / 6.0f;
        b = 0.5f - theta2 / 24.0f;
    } else {
        a = sinf(theta) / theta;
        b = (1.0f - cosf(theta)) / theta2;
    }
    const float R0 = 1.0f - b * (ry * ry + rz * rz);
    const float R1 = -a * rz + b * rx * ry;
    const float R2 =  a * ry + b * rx * rz;
    const float R3 =  a * rz + b * rx * ry;
    const float R4 = 1.0f - b * (rx * rx + rz * rz);
    const float R5 = -a * rx + b * ry * rz;
    const float R6 = -a * ry + b * rx * rz;
    const float R7 =  a * rx + b * ry * rz;
    const float R8 = 1.0f - b * (rx * rx + ry * ry);
    const float t0 = trans[0], t1 = trans[1], t2 = trans[2];

    float4* wb = buf[w];

    // ================= POS =================
    wb[l] = p0;  wb[l + 32] = p1;  wb[l + 64] = p2;
    __syncwarp();
    {
        // lane l owns f4 3l..3l+2 (4 rays); word stride 12 conflict-free.
        float4 a4 = wb[l * 3], b4 = wb[l * 3 + 1], c4 = wb[l * 3 + 2];
        float px[4] = {a4.x, a4.w, b4.z, c4.y};
        float py[4] = {a4.y, b4.x, b4.w, c4.z};
        float pz[4] = {a4.z, b4.y, c4.x, c4.w};
        float ox[4], oy[4], oz[4];
#pragma unroll
        for (int k = 0; k < 4; k++) {
            float x = px[k] - t0;
            float y = py[k] - t1;
            float z = pz[k] - t2;
            ox[k] = fmaf(x, R0, fmaf(y, R3, z * R6));
            oy[k] = fmaf(x, R1, fmaf(y, R4, z * R7));
            oz[k] = fmaf(x, R2, fmaf(y, R5, z * R8));
        }
        // same-lane write-back: no barrier needed between read and write
        wb[l * 3]     = make_float4(ox[0], oy[0], oz[0], ox[1]);
        wb[l * 3 + 1] = make_float4(oy[1], oz[1], ox[2], oy[2]);
        wb[l * 3 + 2] = make_float4(oz[2], ox[3], oy[3], oz[3]);
    }
    __syncwarp();
    out_pos[cbase + l]      = wb[l];
    out_pos[cbase + l + 32] = wb[l + 32];
    out_pos[cbase + l + 64] = wb[l + 64];

    // ================= DIR =================
    // overwrite is same-lane as the reads just above (4l-stride both) -> safe
    wb[l] = d0;  wb[l + 32] = d1;  wb[l + 64] = d2;
    __syncwarp();
    {
        float4 a4 = wb[l * 3], b4 = wb[l * 3 + 1], c4 = wb[l * 3 + 2];
        float px[4] = {a4.x, a4.w, b4.z, c4.y};
        float py[4] = {a4.y, b4.x, b4.w, c4.z};
        float pz[4] = {a4.z, b4.y, c4.x, c4.w};
        float ox[4], oy[4], oz[4];
#pragma unroll
        for (int k = 0; k < 4; k++) {
            float x = px[k];
            float y = py[k];
            float z = pz[k];
            ox[k] = fmaf(x, R0, fmaf(y, R3, z * R6));
            oy[k] = fmaf(x, R1, fmaf(y, R4, z * R7));
            oz[k] = fmaf(x, R2, fmaf(y, R5, z * R8));
        }
        wb[l * 3]     = make_float4(ox[0], oy[0], oz[0], ox[1]);
        wb[l * 3 + 1] = make_float4(oy[1], oz[1], ox[2], oy[2]);
        wb[l * 3 + 2] = make_float4(oz[2], ox[3], oy[3], oz[3]);
    }
    __syncwarp();
    out_dir[cbase + l]      = wb[l];
    out_dir[cbase + l + 32] = wb[l + 32];
    out_dir[cbase + l + 64] = wb[l + 64];
}

extern "C" void kernel_launch(void* const* d_in, const int* in_sizes, int n_in,
                              void* d_out, int out_size) {
    const float* pos = (const float*)d_in[0];      // [N,3]
    const float* dir = (const float*)d_in[1];      // [N,3]
    const float* rot_vec = (const float*)d_in[2];  // [3]
    const float* trans = (const float*)d_in[3];    // [3]

    int n_f4 = in_sizes[0] / 4;  // N*3/4 float4 per stream = 12582912
    float* out = (float*)d_out;
    float* out_pos = out;
    float* out_dir = out + (size_t)out_size / 2;

    int blocks = n_f4 / F4_PER_BLOCK;  // 12582912 / 768 = 16384, exact
    ray_transform_kernel<<<blocks, THREADS>>>(
        (const float4*)pos, (const float4*)dir,
        (float4*)out_pos, (float4*)out_dir, rot_vec, trans);
}

// round 12
// speedup vs baseline: 1.1738x; 1.0083x over previous
#include <cuda_runtime.h>

// RayTransform: local_pos = (pos - trans) @ R, local_dir = dir @ R
// R = exp(skew(rot_vec)). N = 16777216 rays, ~805 MB HBM traffic.
//
// Warp-autonomous (no block barriers) + streaming cache hints:
// all bulk loads/stores use .cs (evict-first) since the stream has zero
// temporal reuse -> minimizes L2 thrash / write-back scheduling pressure.

#define THREADS 256
#define WARPS (THREADS / 32)
#define F4_PER_WARP 96                       // 128 rays per warp per stream
#define F4_PER_BLOCK (WARPS * F4_PER_WARP)   // 768

__global__ void __launch_bounds__(THREADS, 6)
ray_transform_kernel(const float4* __restrict__ pos,
                     const float4* __restrict__ dir,
                     float4* __restrict__ out_pos,
                     float4* __restrict__ out_dir,
                     const float* __restrict__ rot_vec,
                     const float* __restrict__ trans) {
    __shared__ float4 buf[WARPS][F4_PER_WARP];

    const int t = threadIdx.x;
    const int w = t >> 5;
    const int l = t & 31;

    // global chunk base for this warp (in float4 units, per stream)
    const size_t cbase = (size_t)blockIdx.x * F4_PER_BLOCK + w * F4_PER_WARP;

    // ---- all 6 coalesced LDG.128.CS in flight ----
    float4 p0 = __ldcs(pos + cbase + l);
    float4 p1 = __ldcs(pos + cbase + l + 32);
    float4 p2 = __ldcs(pos + cbase + l + 64);
    float4 d0 = __ldcs(dir + cbase + l);
    float4 d1 = __ldcs(dir + cbase + l + 32);
    float4 d2 = __ldcs(dir + cbase + l + 64);

    // ---- per-thread Rodrigues (uniform loads, broadcast) ----
    const float rx = rot_vec[0], ry = rot_vec[1], rz = rot_vec[2];
    const float theta2 = rx * rx + ry * ry + rz * rz;
    const float theta = sqrtf(theta2);
    float a, b;
    if (theta < 1e-8f) {
        a = 1.0f - theta2 / 6.0f;
        b = 0.5f - theta2 / 24.0f;
    } else {
        a = sinf(theta) / theta;
        b = (1.0f - cosf(theta)) / theta2;
    }
    const float R0 = 1.0f - b * (ry * ry + rz * rz);
    const float R1 = -a * rz + b * rx * ry;
    const float R2 =  a * ry + b * rx * rz;
    const float R3 =  a * rz + b * rx * ry;
    const float R4 = 1.0f - b * (rx * rx + rz * rz);
    const float R5 = -a * rx + b * ry * rz;
    const float R6 = -a * ry + b * rx * rz;
    const float R7 =  a * rx + b * ry * rz;
    const float R8 = 1.0f - b * (rx * rx + ry * ry);
    const float t0 = trans[0], t1 = trans[1], t2 = trans[2];

    float4* wb = buf[w];

    // ================= POS =================
    wb[l] = p0;  wb[l + 32] = p1;  wb[l + 64] = p2;
    __syncwarp();
    {
        // lane l owns f4 3l..3l+2 (4 rays); word stride 12 conflict-free.
        float4 a4 = wb[l * 3], b4 = wb[l * 3 + 1], c4 = wb[l * 3 + 2];
        float px[4] = {a4.x, a4.w, b4.z, c4.y};
        float py[4] = {a4.y, b4.x, b4.w, c4.z};
        float pz[4] = {a4.z, b4.y, c4.x, c4.w};
        float ox[4], oy[4], oz[4];
#pragma unroll
        for (int k = 0; k < 4; k++) {
            float x = px[k] - t0;
            float y = py[k] - t1;
            float z = pz[k] - t2;
            ox[k] = fmaf(x, R0, fmaf(y, R3, z * R6));
            oy[k] = fmaf(x, R1, fmaf(y, R4, z * R7));
            oz[k] = fmaf(x, R2, fmaf(y, R5, z * R8));
        }
        // same-lane write-back: no barrier needed between read and write
        wb[l * 3]     = make_float4(ox[0], oy[0], oz[0], ox[1]);
        wb[l * 3 + 1] = make_float4(oy[1], oz[1], ox[2], oy[2]);
        wb[l * 3 + 2] = make_float4(oz[2], ox[3], oy[3], oz[3]);
    }
    __syncwarp();
    __stcs(out_pos + cbase + l,      wb[l]);
    __stcs(out_pos + cbase + l + 32, wb[l + 32]);
    __stcs(out_pos + cbase + l + 64, wb[l + 64]);

    // ================= DIR =================
    // overwrite is same-lane as the reads just above (4l-stride both) -> safe
    wb[l] = d0;  wb[l + 32] = d1;  wb[l + 64] = d2;
    __syncwarp();
    {
        float4 a4 = wb[l * 3], b4 = wb[l * 3 + 1], c4 = wb[l * 3 + 2];
        float px[4] = {a4.x, a4.w, b4.z, c4.y};
        float py[4] = {a4.y, b4.x, b4.w, c4.z};
        float pz[4] = {a4.z, b4.y, c4.x, c4.w};
        float ox[4], oy[4], oz[4];
#pragma unroll
        for (int k = 0; k < 4; k++) {
            float x = px[k];
            float y = py[k];
            float z = pz[k];
            ox[k] = fmaf(x, R0, fmaf(y, R3, z * R6));
            oy[k] = fmaf(x, R1, fmaf(y, R4, z * R7));
            oz[k] = fmaf(x, R2, fmaf(y, R5, z * R8));
        }
        wb[l * 3]     = make_float4(ox[0], oy[0], oz[0], ox[1]);
        wb[l * 3 + 1] = make_float4(oy[1], oz[1], ox[2], oy[2]);
        wb[l * 3 + 2] = make_float4(oz[2], ox[3], oy[3], oz[3]);
    }
    __syncwarp();
    __stcs(out_dir + cbase + l,      wb[l]);
    __stcs(out_dir + cbase + l + 32, wb[l + 32]);
    __stcs(out_dir + cbase + l + 64, wb[l + 64]);
}

extern "C" void kernel_launch(void* const* d_in, const int* in_sizes, int n_in,
                              void* d_out, int out_size) {
    const float* pos = (const float*)d_in[0];      // [N,3]
    const float* dir = (const float*)d_in[1];      // [N,3]
    const float* rot_vec = (const float*)d_in[2];  // [3]
    const float* trans = (const float*)d_in[3];    // [3]

    int n_f4 = in_sizes[0] / 4;  // N*3/4 float4 per stream = 12582912
    float* out = (float*)d_out;
    float* out_pos = out;
    float* out_dir = out + (size_t)out_size / 2;

    int blocks = n_f4 / F4_PER_BLOCK;  // 12582912 / 768 = 16384, exact
    ray_transform_kernel<<<blocks, THREADS>>>(
        (const float4*)pos, (const float4*)dir,
        (float4*)out_pos, (float4*)out_dir, rot_vec, trans);
}